// round 1
// baseline (speedup 1.0000x reference)
#include <cuda_runtime.h>

// ----------------------------------------------------------------------------
// SelfAttention: q=relu(xWq^T+bq), k=..., v=...; P=softmax(qk^T); out=Pv
// Shapes: x[4,2048,1024], W[1024,1024], b[1024]; out[4,2048,1024] fp32
// Round 0: fp32 SGEMM pipeline (128x128x16 tiles, 8x8 microtile, 256 thr).
// ----------------------------------------------------------------------------

namespace {

constexpr int BATCH = 4;
constexpr int SEQ   = 2048;
constexpr int FDIM  = 1024;

// Scratch (device globals: allocation inside kernel_launch is forbidden)
__device__ float g_q[(size_t)BATCH * SEQ * FDIM];
__device__ float g_k[(size_t)BATCH * SEQ * FDIM];
__device__ float g_v[(size_t)BATCH * SEQ * FDIM];
__device__ float g_p[(size_t)BATCH * SEQ * SEQ];   // logits -> scores in place

constexpr int BM = 128, BN = 128, BK = 16;
constexpr int PAD = 4;                 // keeps float4 alignment, spreads banks
constexpr int LDA = BM + PAD;
constexpr int LDB = BN + PAD;

// Generic batched GEMM.
//   TRANS_B = true : C[m,n] = sum_k A[m,k] * B[n,k]   (A:[M,K], B:[N,K] row-major)
//   TRANS_B = false: C[m,n] = sum_k A[m,k] * B[k,n]   (A:[M,K], B:[K,N] row-major)
//   BIAS_RELU: C = relu(C + bias[n])
// All dims must be multiples of the tile sizes (true for every call here).
template<bool BIAS_RELU, bool TRANS_B>
__global__ __launch_bounds__(256, 2)
void gemm_kernel(const float* __restrict__ A, long strideA,
                 const float* __restrict__ Bp, long strideB,
                 float* __restrict__ C, long strideC,
                 const float* __restrict__ bias,
                 int M, int N, int K)
{
    __shared__ float As[BK][LDA];
    __shared__ float Bs[BK][LDB];

    const int tid = threadIdx.x;
    const int m0  = blockIdx.y * BM;
    const int n0  = blockIdx.x * BN;

    A  += (long)blockIdx.z * strideA;
    Bp += (long)blockIdx.z * strideB;
    C  += (long)blockIdx.z * strideC;

    const int tx = tid & 15;       // 0..15 -> 8 cols each
    const int ty = tid >> 4;       // 0..15 -> 8 rows each

    float acc[8][8];
#pragma unroll
    for (int i = 0; i < 8; i++)
#pragma unroll
        for (int j = 0; j < 8; j++) acc[i][j] = 0.0f;

    for (int k0 = 0; k0 < K; k0 += BK) {
        // ---- load A tile [BM x BK], store transposed As[k][m] ----
#pragma unroll
        for (int i = 0; i < 2; i++) {
            int l   = tid + i * 256;          // 0..511
            int row = l >> 2;                 // 0..127
            int kq  = (l & 3) * 4;            // 0,4,8,12
            float4 va = *reinterpret_cast<const float4*>(
                A + (long)(m0 + row) * K + k0 + kq);
            As[kq + 0][row] = va.x;
            As[kq + 1][row] = va.y;
            As[kq + 2][row] = va.z;
            As[kq + 3][row] = va.w;
        }
        // ---- load B tile ----
        if (TRANS_B) {
            // B:[N,K] row-major -> Bs[k][n] (transpose on store)
#pragma unroll
            for (int i = 0; i < 2; i++) {
                int l   = tid + i * 256;
                int row = l >> 2;             // n index 0..127
                int kq  = (l & 3) * 4;
                float4 vb = *reinterpret_cast<const float4*>(
                    Bp + (long)(n0 + row) * K + k0 + kq);
                Bs[kq + 0][row] = vb.x;
                Bs[kq + 1][row] = vb.y;
                Bs[kq + 2][row] = vb.z;
                Bs[kq + 3][row] = vb.w;
            }
        } else {
            // B:[K,N] row-major -> Bs[k][n] direct (coalesced float4)
#pragma unroll
            for (int i = 0; i < 2; i++) {
                int l  = tid + i * 256;       // 512 float4 loads: 16 rows x 32
                int kr = l >> 5;              // 0..15
                int n4 = (l & 31) * 4;        // 0..124
                float4 vb = *reinterpret_cast<const float4*>(
                    Bp + (long)(k0 + kr) * N + n0 + n4);
                *reinterpret_cast<float4*>(&Bs[kr][n4]) = vb;
            }
        }
        __syncthreads();

#pragma unroll
        for (int kk = 0; kk < BK; kk++) {
            float a[8], b[8];
            *reinterpret_cast<float4*>(&a[0]) =
                *reinterpret_cast<const float4*>(&As[kk][ty * 8]);
            *reinterpret_cast<float4*>(&a[4]) =
                *reinterpret_cast<const float4*>(&As[kk][ty * 8 + 4]);
            *reinterpret_cast<float4*>(&b[0]) =
                *reinterpret_cast<const float4*>(&Bs[kk][tx * 8]);
            *reinterpret_cast<float4*>(&b[4]) =
                *reinterpret_cast<const float4*>(&Bs[kk][tx * 8 + 4]);
#pragma unroll
            for (int i = 0; i < 8; i++)
#pragma unroll
                for (int j = 0; j < 8; j++)
                    acc[i][j] = fmaf(a[i], b[j], acc[i][j]);
        }
        __syncthreads();
    }

    // ---- epilogue ----
#pragma unroll
    for (int i = 0; i < 8; i++) {
        long row = m0 + ty * 8 + i;
#pragma unroll
        for (int j = 0; j < 8; j += 4) {
            int col = n0 + tx * 8 + j;
            float4 v;
            v.x = acc[i][j + 0];
            v.y = acc[i][j + 1];
            v.z = acc[i][j + 2];
            v.w = acc[i][j + 3];
            if (BIAS_RELU) {
                v.x = fmaxf(v.x + bias[col + 0], 0.0f);
                v.y = fmaxf(v.y + bias[col + 1], 0.0f);
                v.z = fmaxf(v.z + bias[col + 2], 0.0f);
                v.w = fmaxf(v.w + bias[col + 3], 0.0f);
            }
            *reinterpret_cast<float4*>(C + row * N + col) = v;
        }
    }
}

// One block per row of length 2048; softmax in place.
__global__ __launch_bounds__(256)
void softmax2048(float* __restrict__ P)
{
    const int tid = threadIdx.x;
    float* row = P + (size_t)blockIdx.x * SEQ;

    float4 v0 = reinterpret_cast<float4*>(row)[tid];
    float4 v1 = reinterpret_cast<float4*>(row)[tid + 256];

    float mx = fmaxf(fmaxf(fmaxf(v0.x, v0.y), fmaxf(v0.z, v0.w)),
                     fmaxf(fmaxf(v1.x, v1.y), fmaxf(v1.z, v1.w)));

    __shared__ float red[256];
    red[tid] = mx;
    __syncthreads();
#pragma unroll
    for (int s = 128; s > 0; s >>= 1) {
        if (tid < s) red[tid] = fmaxf(red[tid], red[tid + s]);
        __syncthreads();
    }
    mx = red[0];
    __syncthreads();

    float4 e0, e1;
    e0.x = __expf(v0.x - mx); e0.y = __expf(v0.y - mx);
    e0.z = __expf(v0.z - mx); e0.w = __expf(v0.w - mx);
    e1.x = __expf(v1.x - mx); e1.y = __expf(v1.y - mx);
    e1.z = __expf(v1.z - mx); e1.w = __expf(v1.w - mx);

    float sum = (e0.x + e0.y + e0.z + e0.w) + (e1.x + e1.y + e1.z + e1.w);
    red[tid] = sum;
    __syncthreads();
#pragma unroll
    for (int s = 128; s > 0; s >>= 1) {
        if (tid < s) red[tid] += red[tid + s];
        __syncthreads();
    }
    float inv = 1.0f / red[0];

    e0.x *= inv; e0.y *= inv; e0.z *= inv; e0.w *= inv;
    e1.x *= inv; e1.y *= inv; e1.z *= inv; e1.w *= inv;
    reinterpret_cast<float4*>(row)[tid]       = e0;
    reinterpret_cast<float4*>(row)[tid + 256] = e1;
}

} // namespace

extern "C" void kernel_launch(void* const* d_in, const int* in_sizes, int n_in,
                              void* d_out, int out_size)
{
    const float* x  = (const float*)d_in[0];
    const float* Wq = (const float*)d_in[1];
    const float* bq = (const float*)d_in[2];
    const float* Wk = (const float*)d_in[3];
    const float* bk = (const float*)d_in[4];
    const float* Wv = (const float*)d_in[5];
    const float* bv = (const float*)d_in[6];
    float* out = (float*)d_out;

    float *q, *k, *v, *p;
    cudaGetSymbolAddress((void**)&q, g_q);
    cudaGetSymbolAddress((void**)&k, g_k);
    cudaGetSymbolAddress((void**)&v, g_v);
    cudaGetSymbolAddress((void**)&p, g_p);

    const long SF = (long)SEQ * FDIM;   // per-batch q/k/v stride
    const long SS = (long)SEQ * SEQ;    // per-batch logits stride

    // 1) QKV projections: [8192x1024] @ [1024x1024]^T, bias+ReLU
    {
        dim3 grid(FDIM / BN, (BATCH * SEQ) / BM, 1);
        gemm_kernel<true, true><<<grid, 256>>>(x, 0, Wq, 0, q, 0, bq,
                                               BATCH * SEQ, FDIM, FDIM);
        gemm_kernel<true, true><<<grid, 256>>>(x, 0, Wk, 0, k, 0, bk,
                                               BATCH * SEQ, FDIM, FDIM);
        gemm_kernel<true, true><<<grid, 256>>>(x, 0, Wv, 0, v, 0, bv,
                                               BATCH * SEQ, FDIM, FDIM);
    }

    // 2) logits = q @ k^T per batch: [2048x1024] @ [1024x2048]
    {
        dim3 grid(SEQ / BN, SEQ / BM, BATCH);
        gemm_kernel<false, true><<<grid, 256>>>(q, SF, k, SF, p, SS, nullptr,
                                                SEQ, SEQ, FDIM);
    }

    // 3) softmax over last dim (in place)
    softmax2048<<<BATCH * SEQ, 256>>>(p);

    // 4) out = scores @ v per batch: [2048x2048] @ [2048x1024]
    {
        dim3 grid(FDIM / BN, SEQ / BM, BATCH);
        gemm_kernel<false, false><<<grid, 256>>>(p, SS, v, SF, out, SF, nullptr,
                                                 SEQ, FDIM, SEQ);
    }
}

// round 2
// speedup vs baseline: 1.0017x; 1.0017x over previous
#include <cuda_runtime.h>

// ----------------------------------------------------------------------------
// SelfAttention: q=relu(xWq^T+bq), k=..., v=...; P=softmax(qk^T); out=Pv
// Shapes: x[4,2048,1024], W[1024,1024], b[1024]; out[4,2048,1024] fp32
// Round 0: fp32 SGEMM pipeline (128x128x16 tiles, 8x8 microtile, 256 thr).
// ----------------------------------------------------------------------------

namespace {

constexpr int BATCH = 4;
constexpr int SEQ   = 2048;
constexpr int FDIM  = 1024;

// Scratch (device globals: allocation inside kernel_launch is forbidden)
__device__ float g_q[(size_t)BATCH * SEQ * FDIM];
__device__ float g_k[(size_t)BATCH * SEQ * FDIM];
__device__ float g_v[(size_t)BATCH * SEQ * FDIM];
__device__ float g_p[(size_t)BATCH * SEQ * SEQ];   // logits -> scores in place

constexpr int BM = 128, BN = 128, BK = 16;
constexpr int PAD = 4;                 // keeps float4 alignment, spreads banks
constexpr int LDA = BM + PAD;
constexpr int LDB = BN + PAD;

// Generic batched GEMM.
//   TRANS_B = true : C[m,n] = sum_k A[m,k] * B[n,k]   (A:[M,K], B:[N,K] row-major)
//   TRANS_B = false: C[m,n] = sum_k A[m,k] * B[k,n]   (A:[M,K], B:[K,N] row-major)
//   BIAS_RELU: C = relu(C + bias[n])
// All dims must be multiples of the tile sizes (true for every call here).
template<bool BIAS_RELU, bool TRANS_B>
__global__ __launch_bounds__(256, 2)
void gemm_kernel(const float* __restrict__ A, long strideA,
                 const float* __restrict__ Bp, long strideB,
                 float* __restrict__ C, long strideC,
                 const float* __restrict__ bias,
                 int M, int N, int K)
{
    __shared__ float As[BK][LDA];
    __shared__ float Bs[BK][LDB];

    const int tid = threadIdx.x;
    const int m0  = blockIdx.y * BM;
    const int n0  = blockIdx.x * BN;

    A  += (long)blockIdx.z * strideA;
    Bp += (long)blockIdx.z * strideB;
    C  += (long)blockIdx.z * strideC;

    const int tx = tid & 15;       // 0..15 -> 8 cols each
    const int ty = tid >> 4;       // 0..15 -> 8 rows each

    float acc[8][8];
#pragma unroll
    for (int i = 0; i < 8; i++)
#pragma unroll
        for (int j = 0; j < 8; j++) acc[i][j] = 0.0f;

    for (int k0 = 0; k0 < K; k0 += BK) {
        // ---- load A tile [BM x BK], store transposed As[k][m] ----
#pragma unroll
        for (int i = 0; i < 2; i++) {
            int l   = tid + i * 256;          // 0..511
            int row = l >> 2;                 // 0..127
            int kq  = (l & 3) * 4;            // 0,4,8,12
            float4 va = *reinterpret_cast<const float4*>(
                A + (long)(m0 + row) * K + k0 + kq);
            As[kq + 0][row] = va.x;
            As[kq + 1][row] = va.y;
            As[kq + 2][row] = va.z;
            As[kq + 3][row] = va.w;
        }
        // ---- load B tile ----
        if (TRANS_B) {
            // B:[N,K] row-major -> Bs[k][n] (transpose on store)
#pragma unroll
            for (int i = 0; i < 2; i++) {
                int l   = tid + i * 256;
                int row = l >> 2;             // n index 0..127
                int kq  = (l & 3) * 4;
                float4 vb = *reinterpret_cast<const float4*>(
                    Bp + (long)(n0 + row) * K + k0 + kq);
                Bs[kq + 0][row] = vb.x;
                Bs[kq + 1][row] = vb.y;
                Bs[kq + 2][row] = vb.z;
                Bs[kq + 3][row] = vb.w;
            }
        } else {
            // B:[K,N] row-major -> Bs[k][n] direct (coalesced float4)
#pragma unroll
            for (int i = 0; i < 2; i++) {
                int l  = tid + i * 256;       // 512 float4 loads: 16 rows x 32
                int kr = l >> 5;              // 0..15
                int n4 = (l & 31) * 4;        // 0..124
                float4 vb = *reinterpret_cast<const float4*>(
                    Bp + (long)(k0 + kr) * N + n0 + n4);
                *reinterpret_cast<float4*>(&Bs[kr][n4]) = vb;
            }
        }
        __syncthreads();

#pragma unroll
        for (int kk = 0; kk < BK; kk++) {
            float a[8], b[8];
            *reinterpret_cast<float4*>(&a[0]) =
                *reinterpret_cast<const float4*>(&As[kk][ty * 8]);
            *reinterpret_cast<float4*>(&a[4]) =
                *reinterpret_cast<const float4*>(&As[kk][ty * 8 + 4]);
            *reinterpret_cast<float4*>(&b[0]) =
                *reinterpret_cast<const float4*>(&Bs[kk][tx * 8]);
            *reinterpret_cast<float4*>(&b[4]) =
                *reinterpret_cast<const float4*>(&Bs[kk][tx * 8 + 4]);
#pragma unroll
            for (int i = 0; i < 8; i++)
#pragma unroll
                for (int j = 0; j < 8; j++)
                    acc[i][j] = fmaf(a[i], b[j], acc[i][j]);
        }
        __syncthreads();
    }

    // ---- epilogue ----
#pragma unroll
    for (int i = 0; i < 8; i++) {
        long row = m0 + ty * 8 + i;
#pragma unroll
        for (int j = 0; j < 8; j += 4) {
            int col = n0 + tx * 8 + j;
            float4 v;
            v.x = acc[i][j + 0];
            v.y = acc[i][j + 1];
            v.z = acc[i][j + 2];
            v.w = acc[i][j + 3];
            if (BIAS_RELU) {
                v.x = fmaxf(v.x + bias[col + 0], 0.0f);
                v.y = fmaxf(v.y + bias[col + 1], 0.0f);
                v.z = fmaxf(v.z + bias[col + 2], 0.0f);
                v.w = fmaxf(v.w + bias[col + 3], 0.0f);
            }
            *reinterpret_cast<float4*>(C + row * N + col) = v;
        }
    }
}

// One block per row of length 2048; softmax in place.
__global__ __launch_bounds__(256)
void softmax2048(float* __restrict__ P)
{
    const int tid = threadIdx.x;
    float* row = P + (size_t)blockIdx.x * SEQ;

    float4 v0 = reinterpret_cast<float4*>(row)[tid];
    float4 v1 = reinterpret_cast<float4*>(row)[tid + 256];

    float mx = fmaxf(fmaxf(fmaxf(v0.x, v0.y), fmaxf(v0.z, v0.w)),
                     fmaxf(fmaxf(v1.x, v1.y), fmaxf(v1.z, v1.w)));

    __shared__ float red[256];
    red[tid] = mx;
    __syncthreads();
#pragma unroll
    for (int s = 128; s > 0; s >>= 1) {
        if (tid < s) red[tid] = fmaxf(red[tid], red[tid + s]);
        __syncthreads();
    }
    mx = red[0];
    __syncthreads();

    float4 e0, e1;
    e0.x = __expf(v0.x - mx); e0.y = __expf(v0.y - mx);
    e0.z = __expf(v0.z - mx); e0.w = __expf(v0.w - mx);
    e1.x = __expf(v1.x - mx); e1.y = __expf(v1.y - mx);
    e1.z = __expf(v1.z - mx); e1.w = __expf(v1.w - mx);

    float sum = (e0.x + e0.y + e0.z + e0.w) + (e1.x + e1.y + e1.z + e1.w);
    red[tid] = sum;
    __syncthreads();
#pragma unroll
    for (int s = 128; s > 0; s >>= 1) {
        if (tid < s) red[tid] += red[tid + s];
        __syncthreads();
    }
    float inv = 1.0f / red[0];

    e0.x *= inv; e0.y *= inv; e0.z *= inv; e0.w *= inv;
    e1.x *= inv; e1.y *= inv; e1.z *= inv; e1.w *= inv;
    reinterpret_cast<float4*>(row)[tid]       = e0;
    reinterpret_cast<float4*>(row)[tid + 256] = e1;
}

} // namespace

extern "C" void kernel_launch(void* const* d_in, const int* in_sizes, int n_in,
                              void* d_out, int out_size)
{
    const float* x  = (const float*)d_in[0];
    const float* Wq = (const float*)d_in[1];
    const float* bq = (const float*)d_in[2];
    const float* Wk = (const float*)d_in[3];
    const float* bk = (const float*)d_in[4];
    const float* Wv = (const float*)d_in[5];
    const float* bv = (const float*)d_in[6];
    float* out = (float*)d_out;

    float *q, *k, *v, *p;
    cudaGetSymbolAddress((void**)&q, g_q);
    cudaGetSymbolAddress((void**)&k, g_k);
    cudaGetSymbolAddress((void**)&v, g_v);
    cudaGetSymbolAddress((void**)&p, g_p);

    const long SF = (long)SEQ * FDIM;   // per-batch q/k/v stride
    const long SS = (long)SEQ * SEQ;    // per-batch logits stride

    // 1) QKV projections: [8192x1024] @ [1024x1024]^T, bias+ReLU
    {
        dim3 grid(FDIM / BN, (BATCH * SEQ) / BM, 1);
        gemm_kernel<true, true><<<grid, 256>>>(x, 0, Wq, 0, q, 0, bq,
                                               BATCH * SEQ, FDIM, FDIM);
        gemm_kernel<true, true><<<grid, 256>>>(x, 0, Wk, 0, k, 0, bk,
                                               BATCH * SEQ, FDIM, FDIM);
        gemm_kernel<true, true><<<grid, 256>>>(x, 0, Wv, 0, v, 0, bv,
                                               BATCH * SEQ, FDIM, FDIM);
    }

    // 2) logits = q @ k^T per batch: [2048x1024] @ [1024x2048]
    {
        dim3 grid(SEQ / BN, SEQ / BM, BATCH);
        gemm_kernel<false, true><<<grid, 256>>>(q, SF, k, SF, p, SS, nullptr,
                                                SEQ, SEQ, FDIM);
    }

    // 3) softmax over last dim (in place)
    softmax2048<<<BATCH * SEQ, 256>>>(p);

    // 4) out = scores @ v per batch: [2048x2048] @ [2048x1024]
    {
        dim3 grid(FDIM / BN, SEQ / BM, BATCH);
        gemm_kernel<false, false><<<grid, 256>>>(p, SS, v, SF, out, SF, nullptr,
                                                 SEQ, FDIM, SEQ);
    }
}

// round 4
// speedup vs baseline: 2.4027x; 2.3987x over previous
#include <cuda_runtime.h>
#include <cuda_bf16.h>
#include <cstdint>

namespace {

constexpr int BATCH = 4;
constexpr int SEQ   = 2048;
constexpr int FDIM  = 1024;
constexpr int NTOT  = BATCH * SEQ;   // 8192

// GEMM tiling
constexpr int BM = 128, BN = 128, BK = 64;       // BK in bf16 elems (128B rows)
constexpr int ROW_BYTES   = 144;                 // 128B data + 16B pad (16B-aligned, conflict-free)
constexpr int OPND_BYTES  = 128 * ROW_BYTES;     // 18432
constexpr int STAGE_BYTES = 4 * OPND_BYTES;      // Ah, Al, Bh, Bl = 73728
constexpr int SMEM_BYTES  = 2 * STAGE_BYTES;     // 147456 (double buffered)

// ---------------- device scratch ----------------
__device__ __nv_bfloat16 g_xh[(size_t)NTOT * FDIM];
__device__ __nv_bfloat16 g_xl[(size_t)NTOT * FDIM];
__device__ __nv_bfloat16 g_wh[(size_t)3 * FDIM * FDIM];
__device__ __nv_bfloat16 g_wl[(size_t)3 * FDIM * FDIM];
__device__ __nv_bfloat16 g_qh[(size_t)NTOT * FDIM];
__device__ __nv_bfloat16 g_ql[(size_t)NTOT * FDIM];
__device__ __nv_bfloat16 g_kh[(size_t)NTOT * FDIM];
__device__ __nv_bfloat16 g_kl[(size_t)NTOT * FDIM];
__device__ __nv_bfloat16 g_vth[(size_t)NTOT * FDIM];  // v transposed [b][o][s]
__device__ __nv_bfloat16 g_vtl[(size_t)NTOT * FDIM];
__device__ float         g_logits[(size_t)BATCH * SEQ * SEQ];
__device__ __nv_bfloat16 g_ph[(size_t)BATCH * SEQ * SEQ];
__device__ __nv_bfloat16 g_pl[(size_t)BATCH * SEQ * SEQ];

// ---------------- helpers ----------------
__device__ __forceinline__ uint32_t smem_u32(const void* p) {
    uint32_t a;
    asm("{ .reg .u64 t; cvta.to.shared.u64 t, %1; cvt.u32.u64 %0, t; }"
        : "=r"(a) : "l"(p));
    return a;
}

__device__ __forceinline__ void cp16(uint32_t saddr, const void* gaddr) {
    asm volatile("cp.async.cg.shared.global [%0], [%1], 16;"
                 :: "r"(saddr), "l"(gaddr) : "memory");
}
__device__ __forceinline__ void cp_commit() {
    asm volatile("cp.async.commit_group;" ::: "memory");
}
template<int N>
__device__ __forceinline__ void cp_wait() {
    asm volatile("cp.async.wait_group %0;" :: "n"(N) : "memory");
}

#define LDSM_X4(R, addr) \
    asm volatile("ldmatrix.sync.aligned.m8n8.x4.shared.b16 {%0,%1,%2,%3}, [%4];" \
                 : "=r"((R)[0]), "=r"((R)[1]), "=r"((R)[2]), "=r"((R)[3]) \
                 : "r"(addr))

#define MMA_BF16(D, A, B0, B1) \
    asm volatile("mma.sync.aligned.m16n8k16.row.col.f32.bf16.bf16.f32 " \
                 "{%0,%1,%2,%3}, {%4,%5,%6,%7}, {%8,%9}, {%0,%1,%2,%3};" \
                 : "+f"((D)[0]), "+f"((D)[1]), "+f"((D)[2]), "+f"((D)[3]) \
                 : "r"((A)[0]), "r"((A)[1]), "r"((A)[2]), "r"((A)[3]), \
                   "r"(B0), "r"(B1))

__device__ __forceinline__ void split2(float v, __nv_bfloat16& h, __nv_bfloat16& l) {
    h = __float2bfloat16(v);
    l = __float2bfloat16(v - __bfloat162float(h));
}

// ============================================================================
// hmma_gemm: D[m,n] = sum_k A[m,k]*B[n,k], via AhBh + AhBl + AlBh (fp32 acc)
// EPI 0: fp32 store to dst0 (ld=ldC)
// EPI 1: relu(D+bias) -> bf16 hi/lo row-major (dst0/dst1, ld=ldC)
// EPI 2: relu(D+bias) -> bf16 hi/lo TRANSPOSED per batch [b][o][s]
// ============================================================================
template<int EPI>
__global__ __launch_bounds__(512, 1)
void hmma_gemm(const __nv_bfloat16* __restrict__ Ah, const __nv_bfloat16* __restrict__ Al,
               long sA, int ldA,
               const __nv_bfloat16* __restrict__ Bh, const __nv_bfloat16* __restrict__ Bl,
               long sB, int ldB,
               void* dst0, void* dst1, long sC, int ldC,
               const float* __restrict__ bias, int K)
{
    extern __shared__ char smem[];
    const uint32_t smem_u = smem_u32(smem);

    const int tid = threadIdx.x;
    const int wid = tid >> 5, lid = tid & 31;
    const int warp_m = wid & 3;        // 4 warps over M (32 rows each)
    const int warp_n = wid >> 2;       // 4 warps over N (32 cols each)
    const int m0 = blockIdx.y * BM;
    const int n0 = blockIdx.x * BN;

    Ah += (long)blockIdx.z * sA + (size_t)m0 * ldA;
    Al += (long)blockIdx.z * sA + (size_t)m0 * ldA;
    Bh += (long)blockIdx.z * sB + (size_t)n0 * ldB;
    Bl += (long)blockIdx.z * sB + (size_t)n0 * ldB;

    // loader mapping: 4 operand groups x 128 threads; 8 x 16B segs each
    const int opnd = tid >> 7;
    const int lt   = tid & 127;
    const __nv_bfloat16* lsrc =
        (opnd == 0) ? Ah : (opnd == 1) ? Al : (opnd == 2) ? Bh : Bl;
    const int lld = (opnd < 2) ? ldA : ldB;
    const uint32_t lsm = smem_u + opnd * OPND_BYTES;

    auto issue = [&](int c) {
        const int k0 = c * BK;
        const uint32_t st = lsm + (c & 1) * STAGE_BYTES;
#pragma unroll
        for (int i = 0; i < 8; i++) {
            int seg = lt + i * 128;
            int r = seg >> 3, cs = seg & 7;
            cp16(st + r * ROW_BYTES + cs * 16,
                 lsrc + (size_t)r * lld + k0 + cs * 8);
        }
        cp_commit();
    };

    // ldmatrix lane-constant address parts
    const int q  = lid >> 3, lr = lid & 7;
    const int rowA = (q & 1) * 8 + lr, kA8 = (q >> 1) * 8;   // A: mats m0k0,m8k0,m0k8,m8k8
    const int rowB = (q >> 1) * 8 + lr, kB8 = (q & 1) * 8;   // B: mats n0k0,n0k8,n8k0,n8k8

    float acc[2][4][4];
#pragma unroll
    for (int a = 0; a < 2; a++)
#pragma unroll
        for (int b = 0; b < 4; b++)
#pragma unroll
            for (int cte = 0; cte < 4; cte++) acc[a][b][cte] = 0.0f;

    const int NC = K / BK;
    issue(0);

    for (int c = 0; c < NC; c++) {
        if (c + 1 < NC) { issue(c + 1); cp_wait<1>(); }
        else            { cp_wait<0>(); }
        __syncthreads();

        const uint32_t st = smem_u + (c & 1) * STAGE_BYTES;
        const uint32_t aBaseH = st + (warp_m * 32 + rowA) * ROW_BYTES + kA8 * 2;
        const uint32_t aBaseL = aBaseH + OPND_BYTES;
        const uint32_t bBaseH = st + 2 * OPND_BYTES
                              + (warp_n * 32 + rowB) * ROW_BYTES + kB8 * 2;
        const uint32_t bBaseL = bBaseH + OPND_BYTES;

#pragma unroll
        for (int ks = 0; ks < 4; ks++) {
            const int kb = ks * 32;   // byte offset of k16 step
            uint32_t ah[2][4], al[2][4], bh[2][4], bl[2][4];
#pragma unroll
            for (int tm = 0; tm < 2; tm++) {
                LDSM_X4(ah[tm], aBaseH + tm * 16 * ROW_BYTES + kb);
                LDSM_X4(al[tm], aBaseL + tm * 16 * ROW_BYTES + kb);
            }
#pragma unroll
            for (int p = 0; p < 2; p++) {
                LDSM_X4(bh[p], bBaseH + p * 16 * ROW_BYTES + kb);
                LDSM_X4(bl[p], bBaseL + p * 16 * ROW_BYTES + kb);
            }
#pragma unroll
            for (int tm = 0; tm < 2; tm++) {
#pragma unroll
                for (int p = 0; p < 2; p++) {
#pragma unroll
                    for (int t = 0; t < 2; t++) {
                        float* d = acc[tm][2 * p + t];
                        MMA_BF16(d, ah[tm], bh[p][2 * t], bh[p][2 * t + 1]);
                        MMA_BF16(d, ah[tm], bl[p][2 * t], bl[p][2 * t + 1]);
                        MMA_BF16(d, al[tm], bh[p][2 * t], bh[p][2 * t + 1]);
                    }
                }
            }
        }
        __syncthreads();
    }

    // ----------------- epilogue -----------------
    const int tq  = lid >> 2;            // 0..7
    const int tr2 = (lid & 3) * 2;       // 0,2,4,6

    if (EPI == 0) {
        float* base = (float*)dst0 + (long)blockIdx.z * sC;
#pragma unroll
        for (int tm = 0; tm < 2; tm++) {
            long m = m0 + warp_m * 32 + tm * 16 + tq;
#pragma unroll
            for (int tn = 0; tn < 4; tn++) {
                int n = n0 + warp_n * 32 + tn * 8 + tr2;
                float2 v0 = make_float2(acc[tm][tn][0], acc[tm][tn][1]);
                float2 v1 = make_float2(acc[tm][tn][2], acc[tm][tn][3]);
                *reinterpret_cast<float2*>(base + m * ldC + n)       = v0;
                *reinterpret_cast<float2*>(base + (m + 8) * ldC + n) = v1;
            }
        }
    } else if (EPI == 1) {
        __nv_bfloat16* dh = (__nv_bfloat16*)dst0;
        __nv_bfloat16* dl = (__nv_bfloat16*)dst1;
#pragma unroll
        for (int tm = 0; tm < 2; tm++) {
            long m = m0 + warp_m * 32 + tm * 16 + tq;
#pragma unroll
            for (int tn = 0; tn < 4; tn++) {
                int n = n0 + warp_n * 32 + tn * 8 + tr2;
                float b0 = bias[n], b1 = bias[n + 1];
#pragma unroll
                for (int h = 0; h < 2; h++) {
                    float v0 = fmaxf(acc[tm][tn][2 * h + 0] + b0, 0.0f);
                    float v1 = fmaxf(acc[tm][tn][2 * h + 1] + b1, 0.0f);
                    __nv_bfloat16 h0, l0, h1, l1;
                    split2(v0, h0, l0); split2(v1, h1, l1);
                    long row = m + 8 * h;
                    *reinterpret_cast<__nv_bfloat162*>(dh + row * ldC + n) =
                        __nv_bfloat162(h0, h1);
                    *reinterpret_cast<__nv_bfloat162*>(dl + row * ldC + n) =
                        __nv_bfloat162(l0, l1);
                }
            }
        }
    } else {
        // EPI 2: relu+bias, stage fp32 tile in smem, write transposed hi/lo
        float* smf = (float*)smem;   // [128][132]
#pragma unroll
        for (int tm = 0; tm < 2; tm++) {
            int ml = warp_m * 32 + tm * 16 + tq;
#pragma unroll
            for (int tn = 0; tn < 4; tn++) {
                int nl = warp_n * 32 + tn * 8 + tr2;
                float b0 = bias[n0 + nl], b1 = bias[n0 + nl + 1];
                smf[ml * 132 + nl]           = fmaxf(acc[tm][tn][0] + b0, 0.0f);
                smf[ml * 132 + nl + 1]       = fmaxf(acc[tm][tn][1] + b1, 0.0f);
                smf[(ml + 8) * 132 + nl]     = fmaxf(acc[tm][tn][2] + b0, 0.0f);
                smf[(ml + 8) * 132 + nl + 1] = fmaxf(acc[tm][tn][3] + b1, 0.0f);
            }
        }
        __syncthreads();
        const int o_l  = tid >> 2;          // 0..127 output feature
        const int sblk = (tid & 3) * 32;    // 32 seq elems
        const long bidx = m0 >> 11;
        const long s_g  = (m0 & 2047) + sblk;
        __nv_bfloat16* dh = (__nv_bfloat16*)dst0 + bidx * (long)FDIM * SEQ
                            + (long)(n0 + o_l) * SEQ + s_g;
        __nv_bfloat16* dl = (__nv_bfloat16*)dst1 + bidx * (long)FDIM * SEQ
                            + (long)(n0 + o_l) * SEQ + s_g;
#pragma unroll
        for (int g = 0; g < 32; g += 8) {
            __align__(16) __nv_bfloat16 hb[8], lb[8];
#pragma unroll
            for (int j = 0; j < 8; j++)
                split2(smf[(sblk + g + j) * 132 + o_l], hb[j], lb[j]);
            *reinterpret_cast<uint4*>(dh + g) = *reinterpret_cast<const uint4*>(hb);
            *reinterpret_cast<uint4*>(dl + g) = *reinterpret_cast<const uint4*>(lb);
        }
    }
}

// ---------------- split fp32 -> bf16 hi/lo ----------------
__global__ __launch_bounds__(256)
void split_kernel(const float* __restrict__ s, __nv_bfloat16* __restrict__ h,
                  __nv_bfloat16* __restrict__ l, int n4)
{
    int i = blockIdx.x * blockDim.x + threadIdx.x;
    if (i >= n4) return;
    float4 v = reinterpret_cast<const float4*>(s)[i];
    __align__(8) __nv_bfloat16 hb[4], lb[4];
    split2(v.x, hb[0], lb[0]); split2(v.y, hb[1], lb[1]);
    split2(v.z, hb[2], lb[2]); split2(v.w, hb[3], lb[3]);
    reinterpret_cast<uint2*>(h)[i] = *reinterpret_cast<const uint2*>(hb);
    reinterpret_cast<uint2*>(l)[i] = *reinterpret_cast<const uint2*>(lb);
}

// ---------------- softmax row 2048, split output ----------------
__global__ __launch_bounds__(256)
void softmax_split(const float* __restrict__ L, __nv_bfloat16* __restrict__ ph,
                   __nv_bfloat16* __restrict__ pl)
{
    const int tid = threadIdx.x;
    const float* row = L + (size_t)blockIdx.x * SEQ;

    float4 v0 = reinterpret_cast<const float4*>(row)[tid];
    float4 v1 = reinterpret_cast<const float4*>(row)[tid + 256];

    float mx = fmaxf(fmaxf(fmaxf(v0.x, v0.y), fmaxf(v0.z, v0.w)),
                     fmaxf(fmaxf(v1.x, v1.y), fmaxf(v1.z, v1.w)));
    __shared__ float red[256];
    red[tid] = mx; __syncthreads();
#pragma unroll
    for (int s = 128; s > 0; s >>= 1) {
        if (tid < s) red[tid] = fmaxf(red[tid], red[tid + s]);
        __syncthreads();
    }
    mx = red[0]; __syncthreads();

    float e0x = __expf(v0.x - mx), e0y = __expf(v0.y - mx);
    float e0z = __expf(v0.z - mx), e0w = __expf(v0.w - mx);
    float e1x = __expf(v1.x - mx), e1y = __expf(v1.y - mx);
    float e1z = __expf(v1.z - mx), e1w = __expf(v1.w - mx);

    float sum = (e0x + e0y + e0z + e0w) + (e1x + e1y + e1z + e1w);
    red[tid] = sum; __syncthreads();
#pragma unroll
    for (int s = 128; s > 0; s >>= 1) {
        if (tid < s) red[tid] += red[tid + s];
        __syncthreads();
    }
    float inv = 1.0f / red[0];

    __nv_bfloat16* ph_row = ph + (size_t)blockIdx.x * SEQ;
    __nv_bfloat16* pl_row = pl + (size_t)blockIdx.x * SEQ;
    __align__(8) __nv_bfloat16 hb[4], lb[4];

    split2(e0x * inv, hb[0], lb[0]); split2(e0y * inv, hb[1], lb[1]);
    split2(e0z * inv, hb[2], lb[2]); split2(e0w * inv, hb[3], lb[3]);
    reinterpret_cast<uint2*>(ph_row)[tid] = *reinterpret_cast<const uint2*>(hb);
    reinterpret_cast<uint2*>(pl_row)[tid] = *reinterpret_cast<const uint2*>(lb);

    split2(e1x * inv, hb[0], lb[0]); split2(e1y * inv, hb[1], lb[1]);
    split2(e1z * inv, hb[2], lb[2]); split2(e1w * inv, hb[3], lb[3]);
    reinterpret_cast<uint2*>(ph_row)[tid + 256] = *reinterpret_cast<const uint2*>(hb);
    reinterpret_cast<uint2*>(pl_row)[tid + 256] = *reinterpret_cast<const uint2*>(lb);
}

} // namespace

extern "C" void kernel_launch(void* const* d_in, const int* in_sizes, int n_in,
                              void* d_out, int out_size)
{
    const float* x  = (const float*)d_in[0];
    const float* Wq = (const float*)d_in[1];
    const float* bq = (const float*)d_in[2];
    const float* Wk = (const float*)d_in[3];
    const float* bk = (const float*)d_in[4];
    const float* Wv = (const float*)d_in[5];
    const float* bv = (const float*)d_in[6];
    float* out = (float*)d_out;

    __nv_bfloat16 *xh, *xl, *wh, *wl, *qh, *ql, *kh, *kl, *vth, *vtl, *ph, *pl;
    float* logits;
    cudaGetSymbolAddress((void**)&xh, g_xh);   cudaGetSymbolAddress((void**)&xl, g_xl);
    cudaGetSymbolAddress((void**)&wh, g_wh);   cudaGetSymbolAddress((void**)&wl, g_wl);
    cudaGetSymbolAddress((void**)&qh, g_qh);   cudaGetSymbolAddress((void**)&ql, g_ql);
    cudaGetSymbolAddress((void**)&kh, g_kh);   cudaGetSymbolAddress((void**)&kl, g_kl);
    cudaGetSymbolAddress((void**)&vth, g_vth); cudaGetSymbolAddress((void**)&vtl, g_vtl);
    cudaGetSymbolAddress((void**)&ph, g_ph);   cudaGetSymbolAddress((void**)&pl, g_pl);
    cudaGetSymbolAddress((void**)&logits, g_logits);

    cudaFuncSetAttribute(hmma_gemm<0>, cudaFuncAttributeMaxDynamicSharedMemorySize, SMEM_BYTES);
    cudaFuncSetAttribute(hmma_gemm<1>, cudaFuncAttributeMaxDynamicSharedMemorySize, SMEM_BYTES);
    cudaFuncSetAttribute(hmma_gemm<2>, cudaFuncAttributeMaxDynamicSharedMemorySize, SMEM_BYTES);

    const long WSZ = (long)FDIM * FDIM;
    const long SF  = (long)SEQ * FDIM;
    const long SS  = (long)SEQ * SEQ;

    // 1) splits
    {
        int n4x = (NTOT * FDIM) / 4;
        split_kernel<<<(n4x + 255) / 256, 256>>>(x, xh, xl, n4x);
        int n4w = (FDIM * FDIM) / 4;
        split_kernel<<<(n4w + 255) / 256, 256>>>(Wq, wh + 0 * WSZ, wl + 0 * WSZ, n4w);
        split_kernel<<<(n4w + 255) / 256, 256>>>(Wk, wh + 1 * WSZ, wl + 1 * WSZ, n4w);
        split_kernel<<<(n4w + 255) / 256, 256>>>(Wv, wh + 2 * WSZ, wl + 2 * WSZ, n4w);
    }

    // 2) projections: q,k row-major hi/lo; v transposed hi/lo
    {
        dim3 grid(FDIM / BN, NTOT / BM, 1);
        hmma_gemm<1><<<grid, 512, SMEM_BYTES>>>(xh, xl, 0, FDIM,
                                                wh + 0 * WSZ, wl + 0 * WSZ, 0, FDIM,
                                                qh, ql, 0, FDIM, bq, FDIM);
        hmma_gemm<1><<<grid, 512, SMEM_BYTES>>>(xh, xl, 0, FDIM,
                                                wh + 1 * WSZ, wl + 1 * WSZ, 0, FDIM,
                                                kh, kl, 0, FDIM, bk, FDIM);
        hmma_gemm<2><<<grid, 512, SMEM_BYTES>>>(xh, xl, 0, FDIM,
                                                wh + 2 * WSZ, wl + 2 * WSZ, 0, FDIM,
                                                vth, vtl, 0, FDIM, bv, FDIM);
    }

    // 3) logits = q k^T per batch
    {
        dim3 grid(SEQ / BN, SEQ / BM, BATCH);
        hmma_gemm<0><<<grid, 512, SMEM_BYTES>>>(qh, ql, SF, FDIM,
                                                kh, kl, SF, FDIM,
                                                logits, nullptr, SS, SEQ, nullptr, FDIM);
    }

    // 4) softmax -> P hi/lo
    softmax_split<<<BATCH * SEQ, 256>>>(logits, ph, pl);

    // 5) out = P v per batch (B operand = v transposed [o][s])
    {
        dim3 grid(FDIM / BN, SEQ / BM, BATCH);
        hmma_gemm<0><<<grid, 512, SMEM_BYTES>>>(ph, pl, SS, SEQ,
                                                vth, vtl, (long)FDIM * SEQ, SEQ,
                                                out, nullptr, SF, FDIM, nullptr, SEQ);
    }
}

// round 6
// speedup vs baseline: 2.6760x; 1.1137x over previous
#include <cuda_runtime.h>
#include <cuda_bf16.h>
#include <cstdint>

namespace {

constexpr int BATCH = 4;
constexpr int SEQ   = 2048;
constexpr int FDIM  = 1024;
constexpr int NTOT  = BATCH * SEQ;   // 8192

constexpr int BM = 128, BN = 128, BK = 64;       // BK bf16 elems (128B rows)
constexpr int ROW_BYTES   = 144;                 // 128B data + 16B pad
constexpr int OPND_BYTES  = 128 * ROW_BYTES;     // 18432
constexpr int STAGE_BYTES = 4 * OPND_BYTES;      // 73728
constexpr int SMEM_BYTES  = 2 * STAGE_BYTES;     // 147456

// ---------------- device scratch ----------------
__device__ __nv_bfloat16 g_xh[(size_t)NTOT * FDIM];
__device__ __nv_bfloat16 g_xl[(size_t)NTOT * FDIM];
__device__ __nv_bfloat16 g_wh[(size_t)3 * FDIM * FDIM];
__device__ __nv_bfloat16 g_wl[(size_t)3 * FDIM * FDIM];
__device__ __nv_bfloat16 g_qh[(size_t)NTOT * FDIM];
__device__ __nv_bfloat16 g_ql[(size_t)NTOT * FDIM];
__device__ __nv_bfloat16 g_kh[(size_t)NTOT * FDIM];
__device__ __nv_bfloat16 g_kl[(size_t)NTOT * FDIM];
__device__ __nv_bfloat16 g_vth[(size_t)NTOT * FDIM];  // v transposed [b][o][s]
__device__ __nv_bfloat16 g_vtl[(size_t)NTOT * FDIM];
__device__ float         g_logits[(size_t)BATCH * SEQ * SEQ];
__device__ __nv_bfloat16 g_ph[(size_t)BATCH * SEQ * SEQ];
__device__ __nv_bfloat16 g_pl[(size_t)BATCH * SEQ * SEQ];

// ---------------- helpers ----------------
__device__ __forceinline__ uint32_t smem_u32(const void* p) {
    uint32_t a;
    asm("{ .reg .u64 t; cvta.to.shared.u64 t, %1; cvt.u32.u64 %0, t; }"
        : "=r"(a) : "l"(p));
    return a;
}
__device__ __forceinline__ void cp16(uint32_t saddr, const void* gaddr) {
    asm volatile("cp.async.cg.shared.global [%0], [%1], 16;"
                 :: "r"(saddr), "l"(gaddr) : "memory");
}
__device__ __forceinline__ void cp_commit() {
    asm volatile("cp.async.commit_group;" ::: "memory");
}
template<int N>
__device__ __forceinline__ void cp_wait() {
    asm volatile("cp.async.wait_group %0;" :: "n"(N) : "memory");
}

#define LDSM_X4(R, addr) \
    asm volatile("ldmatrix.sync.aligned.m8n8.x4.shared.b16 {%0,%1,%2,%3}, [%4];" \
                 : "=r"((R)[0]), "=r"((R)[1]), "=r"((R)[2]), "=r"((R)[3]) \
                 : "r"(addr))

#define MMA_BF16(D, A, B0, B1) \
    asm volatile("mma.sync.aligned.m16n8k16.row.col.f32.bf16.bf16.f32 " \
                 "{%0,%1,%2,%3}, {%4,%5,%6,%7}, {%8,%9}, {%0,%1,%2,%3};" \
                 : "+f"((D)[0]), "+f"((D)[1]), "+f"((D)[2]), "+f"((D)[3]) \
                 : "r"((A)[0]), "r"((A)[1]), "r"((A)[2]), "r"((A)[3]), \
                   "r"(B0), "r"(B1))

__device__ __forceinline__ void split2(float v, __nv_bfloat16& h, __nv_bfloat16& l) {
    h = __float2bfloat16(v);
    l = __float2bfloat16(v - __bfloat162float(h));
}

// ============================================================================
// Mainloop: acc[4][4][4] per thread. Warp grid 2(M)x4(N); warp tile 64x32.
// Terms: AhBh + AhBl + AlBh (fp32 acc). A/B pre-offset to (m0|n0, 0).
// ============================================================================
__device__ __forceinline__ void run_mainloop(
    const __nv_bfloat16* __restrict__ Ah, const __nv_bfloat16* __restrict__ Al,
    const __nv_bfloat16* __restrict__ Bh, const __nv_bfloat16* __restrict__ Bl,
    int ldA, int ldB, int K, uint32_t smem_u, int tid,
    float acc[4][4][4])
{
    const int wid = tid >> 5, lid = tid & 31;
    const int warp_m = wid & 1, warp_n = wid >> 1;
    const int q = lid >> 3, lr = lid & 7;
    const int rowA = (q & 1) * 8 + lr, kA8 = (q >> 1) * 8;
    const int rowB = (q >> 1) * 8 + lr, kB8 = (q & 1) * 8;

    const __nv_bfloat16* srcs[4] = {Ah, Al, Bh, Bl};
    const int lds[4] = {ldA, ldA, ldB, ldB};

    auto issue = [&](int c) {
        const int k0 = c * BK;
        const uint32_t st = smem_u + (c & 1) * STAGE_BYTES;
#pragma unroll
        for (int op = 0; op < 4; op++) {
#pragma unroll
            for (int i = 0; i < 4; i++) {
                int seg = i * 256 + tid;
                int r = seg >> 3, cs = seg & 7;
                cp16(st + op * OPND_BYTES + r * ROW_BYTES + cs * 16,
                     srcs[op] + (size_t)r * lds[op] + k0 + cs * 8);
            }
        }
        cp_commit();
    };

    const int NC = K / BK;
    issue(0);

    for (int c = 0; c < NC; c++) {
        if (c + 1 < NC) { issue(c + 1); cp_wait<1>(); }
        else            { cp_wait<0>(); }
        __syncthreads();

        const uint32_t st = smem_u + (c & 1) * STAGE_BYTES;
        const uint32_t aH = st + (warp_m * 64 + rowA) * ROW_BYTES + kA8 * 2;
        const uint32_t aL = aH + OPND_BYTES;
        const uint32_t bH = st + 2 * OPND_BYTES
                          + (warp_n * 32 + rowB) * ROW_BYTES + kB8 * 2;
        const uint32_t bL = bH + OPND_BYTES;

#pragma unroll
        for (int ks = 0; ks < 4; ks++) {
            const int kb = ks * 32;
            uint32_t ah[4][4], al[4][4], bh[2][4], bl[2][4];
#pragma unroll
            for (int t = 0; t < 4; t++) {
                LDSM_X4(ah[t], aH + t * 16 * ROW_BYTES + kb);
                LDSM_X4(al[t], aL + t * 16 * ROW_BYTES + kb);
            }
#pragma unroll
            for (int p = 0; p < 2; p++) {
                LDSM_X4(bh[p], bH + p * 16 * ROW_BYTES + kb);
                LDSM_X4(bl[p], bL + p * 16 * ROW_BYTES + kb);
            }
#pragma unroll
            for (int t = 0; t < 4; t++) {
#pragma unroll
                for (int p = 0; p < 2; p++) {
#pragma unroll
                    for (int h = 0; h < 2; h++) {
                        float* d = acc[t][2 * p + h];
                        MMA_BF16(d, ah[t], bh[p][2 * h], bh[p][2 * h + 1]);
                        MMA_BF16(d, ah[t], bl[p][2 * h], bl[p][2 * h + 1]);
                        MMA_BF16(d, al[t], bh[p][2 * h], bh[p][2 * h + 1]);
                    }
                }
            }
        }
        __syncthreads();
    }
}

// ============================================================================
// Generic batched GEMM (fp32 epilogue): D[m,n] = sum_k A[m,k]*B[n,k]
// ============================================================================
__global__ __launch_bounds__(256, 1)
void gemm_f32(const __nv_bfloat16* __restrict__ Ah, const __nv_bfloat16* __restrict__ Al,
              long sA, int ldA,
              const __nv_bfloat16* __restrict__ Bh, const __nv_bfloat16* __restrict__ Bl,
              long sB, int ldB,
              float* __restrict__ dst, long sC, int ldC, int K)
{
    extern __shared__ char smem[];
    const uint32_t smem_u = smem_u32(smem);
    const int tid = threadIdx.x;
    const int wid = tid >> 5, lid = tid & 31;
    const int warp_m = wid & 1, warp_n = wid >> 1;
    const int m0 = blockIdx.y * BM, n0 = blockIdx.x * BN;

    const __nv_bfloat16* ah = Ah + (long)blockIdx.z * sA + (size_t)m0 * ldA;
    const __nv_bfloat16* al = Al + (long)blockIdx.z * sA + (size_t)m0 * ldA;
    const __nv_bfloat16* bh = Bh + (long)blockIdx.z * sB + (size_t)n0 * ldB;
    const __nv_bfloat16* bl = Bl + (long)blockIdx.z * sB + (size_t)n0 * ldB;

    float acc[4][4][4];
#pragma unroll
    for (int t = 0; t < 4; t++)
#pragma unroll
        for (int n = 0; n < 4; n++)
#pragma unroll
            for (int e = 0; e < 4; e++) acc[t][n][e] = 0.0f;

    run_mainloop(ah, al, bh, bl, ldA, ldB, K, smem_u, tid, acc);

    const int tq = lid >> 2, tr2 = (lid & 3) * 2;
    float* base = dst + (long)blockIdx.z * sC;
#pragma unroll
    for (int t = 0; t < 4; t++) {
        long m = m0 + warp_m * 64 + t * 16 + tq;
#pragma unroll
        for (int tn = 0; tn < 4; tn++) {
            int n = n0 + warp_n * 32 + tn * 8 + tr2;
            *reinterpret_cast<float2*>(base + m * ldC + n) =
                make_float2(acc[t][tn][0], acc[t][tn][1]);
            *reinterpret_cast<float2*>(base + (m + 8) * ldC + n) =
                make_float2(acc[t][tn][2], acc[t][tn][3]);
        }
    }
}

// ============================================================================
// Fused projection kernel: z=0 -> q (hi/lo), z=1 -> k (hi/lo),
// z=2 -> v transposed (hi/lo). relu(x W^T + b).
// ============================================================================
__global__ __launch_bounds__(256, 1)
void proj_kernel(const __nv_bfloat16* __restrict__ xh, const __nv_bfloat16* __restrict__ xl,
                 const __nv_bfloat16* __restrict__ wh, const __nv_bfloat16* __restrict__ wl,
                 const float* __restrict__ bq, const float* __restrict__ bk,
                 const float* __restrict__ bv,
                 __nv_bfloat16* __restrict__ qh, __nv_bfloat16* __restrict__ ql,
                 __nv_bfloat16* __restrict__ kh, __nv_bfloat16* __restrict__ kl,
                 __nv_bfloat16* __restrict__ vth, __nv_bfloat16* __restrict__ vtl)
{
    extern __shared__ char smem[];
    const uint32_t smem_u = smem_u32(smem);
    const int tid = threadIdx.x;
    const int wid = tid >> 5, lid = tid & 31;
    const int warp_m = wid & 1, warp_n = wid >> 1;
    const int m0 = blockIdx.y * BM, n0 = blockIdx.x * BN;
    const int z = blockIdx.z;
    const long WSZ = (long)FDIM * FDIM;

    const float* bias = (z == 0) ? bq : (z == 1) ? bk : bv;
    const __nv_bfloat16* ah = xh + (size_t)m0 * FDIM;
    const __nv_bfloat16* al = xl + (size_t)m0 * FDIM;
    const __nv_bfloat16* bhp = wh + z * WSZ + (size_t)n0 * FDIM;
    const __nv_bfloat16* blp = wl + z * WSZ + (size_t)n0 * FDIM;

    float acc[4][4][4];
#pragma unroll
    for (int t = 0; t < 4; t++)
#pragma unroll
        for (int n = 0; n < 4; n++)
#pragma unroll
            for (int e = 0; e < 4; e++) acc[t][n][e] = 0.0f;

    run_mainloop(ah, al, bhp, blp, FDIM, FDIM, FDIM, smem_u, tid, acc);

    const int tq = lid >> 2, tr2 = (lid & 3) * 2;

    if (z < 2) {
        __nv_bfloat16* dh = (z == 0) ? qh : kh;
        __nv_bfloat16* dl = (z == 0) ? ql : kl;
#pragma unroll
        for (int t = 0; t < 4; t++) {
            long m = m0 + warp_m * 64 + t * 16 + tq;
#pragma unroll
            for (int tn = 0; tn < 4; tn++) {
                int n = n0 + warp_n * 32 + tn * 8 + tr2;
                float b0 = bias[n], b1 = bias[n + 1];
#pragma unroll
                for (int h = 0; h < 2; h++) {
                    float v0 = fmaxf(acc[t][tn][2 * h + 0] + b0, 0.0f);
                    float v1 = fmaxf(acc[t][tn][2 * h + 1] + b1, 0.0f);
                    __nv_bfloat16 h0, l0, h1, l1;
                    split2(v0, h0, l0); split2(v1, h1, l1);
                    long row = m + 8 * h;
                    *reinterpret_cast<__nv_bfloat162*>(dh + row * FDIM + n) =
                        __nv_bfloat162(h0, h1);
                    *reinterpret_cast<__nv_bfloat162*>(dl + row * FDIM + n) =
                        __nv_bfloat162(l0, l1);
                }
            }
        }
    } else {
        // v: relu+bias, stage fp32 in smem, write transposed bf16 hi/lo
        float* smf = (float*)smem;   // [128][132]
#pragma unroll
        for (int t = 0; t < 4; t++) {
            int ml = warp_m * 64 + t * 16 + tq;
#pragma unroll
            for (int tn = 0; tn < 4; tn++) {
                int nl = warp_n * 32 + tn * 8 + tr2;
                float b0 = bias[n0 + nl], b1 = bias[n0 + nl + 1];
                smf[ml * 132 + nl]           = fmaxf(acc[t][tn][0] + b0, 0.0f);
                smf[ml * 132 + nl + 1]       = fmaxf(acc[t][tn][1] + b1, 0.0f);
                smf[(ml + 8) * 132 + nl]     = fmaxf(acc[t][tn][2] + b0, 0.0f);
                smf[(ml + 8) * 132 + nl + 1] = fmaxf(acc[t][tn][3] + b1, 0.0f);
            }
        }
        __syncthreads();
        const int o_l  = tid >> 1;           // 0..127 output feature
        const int sblk = (tid & 1) * 64;     // 64 seq elems
        const long bidx = m0 >> 11;
        const long s_g  = (m0 & 2047) + sblk;
        __nv_bfloat16* dh = vth + bidx * (long)FDIM * SEQ
                            + (long)(n0 + o_l) * SEQ + s_g;
        __nv_bfloat16* dl = vtl + bidx * (long)FDIM * SEQ
                            + (long)(n0 + o_l) * SEQ + s_g;
#pragma unroll
        for (int g = 0; g < 64; g += 8) {
            __align__(16) __nv_bfloat16 hb[8], lb[8];
#pragma unroll
            for (int j = 0; j < 8; j++)
                split2(smf[(sblk + g + j) * 132 + o_l], hb[j], lb[j]);
            *reinterpret_cast<uint4*>(dh + g) = *reinterpret_cast<const uint4*>(hb);
            *reinterpret_cast<uint4*>(dl + g) = *reinterpret_cast<const uint4*>(lb);
        }
    }
}

// ---------------- split fp32 -> bf16 hi/lo ----------------
__global__ __launch_bounds__(256)
void split_kernel(const float* __restrict__ s, __nv_bfloat16* __restrict__ h,
                  __nv_bfloat16* __restrict__ l, int n4)
{
    int i = blockIdx.x * blockDim.x + threadIdx.x;
    if (i >= n4) return;
    float4 v = reinterpret_cast<const float4*>(s)[i];
    __align__(8) __nv_bfloat16 hb[4], lb[4];
    split2(v.x, hb[0], lb[0]); split2(v.y, hb[1], lb[1]);
    split2(v.z, hb[2], lb[2]); split2(v.w, hb[3], lb[3]);
    reinterpret_cast<uint2*>(h)[i] = *reinterpret_cast<const uint2*>(hb);
    reinterpret_cast<uint2*>(l)[i] = *reinterpret_cast<const uint2*>(lb);
}

// ---------------- softmax row 2048, split output ----------------
__global__ __launch_bounds__(256)
void softmax_split(const float* __restrict__ L, __nv_bfloat16* __restrict__ ph,
                   __nv_bfloat16* __restrict__ pl)
{
    const int tid = threadIdx.x;
    const float* row = L + (size_t)blockIdx.x * SEQ;

    float4 v0 = reinterpret_cast<const float4*>(row)[tid];
    float4 v1 = reinterpret_cast<const float4*>(row)[tid + 256];

    float mx = fmaxf(fmaxf(fmaxf(v0.x, v0.y), fmaxf(v0.z, v0.w)),
                     fmaxf(fmaxf(v1.x, v1.y), fmaxf(v1.z, v1.w)));
    __shared__ float red[256];
    red[tid] = mx; __syncthreads();
#pragma unroll
    for (int s = 128; s > 0; s >>= 1) {
        if (tid < s) red[tid] = fmaxf(red[tid], red[tid + s]);
        __syncthreads();
    }
    mx = red[0]; __syncthreads();

    float e0x = __expf(v0.x - mx), e0y = __expf(v0.y - mx);
    float e0z = __expf(v0.z - mx), e0w = __expf(v0.w - mx);
    float e1x = __expf(v1.x - mx), e1y = __expf(v1.y - mx);
    float e1z = __expf(v1.z - mx), e1w = __expf(v1.w - mx);

    float sum = (e0x + e0y + e0z + e0w) + (e1x + e1y + e1z + e1w);
    red[tid] = sum; __syncthreads();
#pragma unroll
    for (int s = 128; s > 0; s >>= 1) {
        if (tid < s) red[tid] += red[tid + s];
        __syncthreads();
    }
    float inv = 1.0f / red[0];

    __nv_bfloat16* ph_row = ph + (size_t)blockIdx.x * SEQ;
    __nv_bfloat16* pl_row = pl + (size_t)blockIdx.x * SEQ;
    __align__(8) __nv_bfloat16 hb[4], lb[4];

    split2(e0x * inv, hb[0], lb[0]); split2(e0y * inv, hb[1], lb[1]);
    split2(e0z * inv, hb[2], lb[2]); split2(e0w * inv, hb[3], lb[3]);
    reinterpret_cast<uint2*>(ph_row)[tid] = *reinterpret_cast<const uint2*>(hb);
    reinterpret_cast<uint2*>(pl_row)[tid] = *reinterpret_cast<const uint2*>(lb);

    split2(e1x * inv, hb[0], lb[0]); split2(e1y * inv, hb[1], lb[1]);
    split2(e1z * inv, hb[2], lb[2]); split2(e1w * inv, hb[3], lb[3]);
    reinterpret_cast<uint2*>(ph_row)[tid + 256] = *reinterpret_cast<const uint2*>(hb);
    reinterpret_cast<uint2*>(pl_row)[tid + 256] = *reinterpret_cast<const uint2*>(lb);
}

} // namespace

extern "C" void kernel_launch(void* const* d_in, const int* in_sizes, int n_in,
                              void* d_out, int out_size)
{
    const float* x  = (const float*)d_in[0];
    const float* Wq = (const float*)d_in[1];
    const float* bq = (const float*)d_in[2];
    const float* Wk = (const float*)d_in[3];
    const float* bk = (const float*)d_in[4];
    const float* Wv = (const float*)d_in[5];
    const float* bv = (const float*)d_in[6];
    float* out = (float*)d_out;

    __nv_bfloat16 *xh, *xl, *wh, *wl, *qh, *ql, *kh, *kl, *vth, *vtl, *ph, *pl;
    float* logits;
    cudaGetSymbolAddress((void**)&xh, g_xh);   cudaGetSymbolAddress((void**)&xl, g_xl);
    cudaGetSymbolAddress((void**)&wh, g_wh);   cudaGetSymbolAddress((void**)&wl, g_wl);
    cudaGetSymbolAddress((void**)&qh, g_qh);   cudaGetSymbolAddress((void**)&ql, g_ql);
    cudaGetSymbolAddress((void**)&kh, g_kh);   cudaGetSymbolAddress((void**)&kl, g_kl);
    cudaGetSymbolAddress((void**)&vth, g_vth); cudaGetSymbolAddress((void**)&vtl, g_vtl);
    cudaGetSymbolAddress((void**)&ph, g_ph);   cudaGetSymbolAddress((void**)&pl, g_pl);
    cudaGetSymbolAddress((void**)&logits, g_logits);

    cudaFuncSetAttribute(proj_kernel, cudaFuncAttributeMaxDynamicSharedMemorySize, SMEM_BYTES);
    cudaFuncSetAttribute(gemm_f32,    cudaFuncAttributeMaxDynamicSharedMemorySize, SMEM_BYTES);

    const long WSZ = (long)FDIM * FDIM;
    const long SF  = (long)SEQ * FDIM;
    const long SS  = (long)SEQ * SEQ;

    // 1) splits
    {
        int n4x = (NTOT * FDIM) / 4;
        split_kernel<<<(n4x + 255) / 256, 256>>>(x, xh, xl, n4x);
        int n4w = (FDIM * FDIM) / 4;
        split_kernel<<<(n4w + 255) / 256, 256>>>(Wq, wh + 0 * WSZ, wl + 0 * WSZ, n4w);
        split_kernel<<<(n4w + 255) / 256, 256>>>(Wk, wh + 1 * WSZ, wl + 1 * WSZ, n4w);
        split_kernel<<<(n4w + 255) / 256, 256>>>(Wv, wh + 2 * WSZ, wl + 2 * WSZ, n4w);
    }

    // 2) fused projections (q, k, v-transposed)
    {
        dim3 grid(FDIM / BN, NTOT / BM, 3);
        proj_kernel<<<grid, 256, SMEM_BYTES>>>(xh, xl, wh, wl, bq, bk, bv,
                                               qh, ql, kh, kl, vth, vtl);
    }

    // 3) logits = q k^T per batch
    {
        dim3 grid(SEQ / BN, SEQ / BM, BATCH);
        gemm_f32<<<grid, 256, SMEM_BYTES>>>(qh, ql, SF, FDIM,
                                            kh, kl, SF, FDIM,
                                            logits, SS, SEQ, FDIM);
    }

    // 4) softmax -> P hi/lo
    softmax_split<<<BATCH * SEQ, 256>>>(logits, ph, pl);

    // 5) out = P v per batch (3-term, B = v^T hi/lo)
    {
        dim3 grid(FDIM / BN, SEQ / BM, BATCH);
        gemm_f32<<<grid, 256, SMEM_BYTES>>>(ph, pl, SS, SEQ,
                                            vth, vtl, (long)FDIM * SEQ, SEQ,
                                            out, SF, FDIM, SEQ);
    }
}